// round 13
// baseline (speedup 1.0000x reference)
#include <cuda_runtime.h>
#include <cuda_fp16.h>
#include <math.h>
#include <stdint.h>

#define L_LAYERS 250
#define N_TRACES 600
#define N_THETA  30
#define NI   249                 // interfaces (ref row 249 is zero -> dropped)
#define NCOL 18000               // N_TRACES * N_THETA
#define NP   18048               // padded R plane pitch (cols)
#define KPAD 256                 // padded K
#define TOTAL (NI * NCOL)
#define HTOTAL (TOTAL / 2)       // angle-pair count
#define WELEMS (256 * 256)

// fp16 planes. __device__ globals are zero-initialized at module load.
// Pad regions (rows >= 249, cols >= 18000) are NEVER written by any kernel,
// so they remain zero across all graph replays.
__device__ __half g_Rh[KPAD * NP];
__device__ __half g_Wh[256 * 256];

__device__ __forceinline__ float sqrt_approx(float x) {
    float r;
    asm("sqrt.approx.f32 %0, %1;" : "=f"(r) : "f"(x));
    return r;
}

// ---------------------------------------------------------------------------
// Phase 1 (fused): exact Zoeppritz Rpp via the Aki & Richards closed form,
// rescaled by a1*a2*b1*b2 (one rcp + one final divide per angle). One thread
// computes TWO adjacent angles -> __half2 store. Clipping never activates for
// these input ranges (p*a2 <= 0.836).
// Blocks past the pair range convert W fp32 -> fp16.   (round-8 proven)
// ---------------------------------------------------------------------------
__global__ void zoe_phase1(const float* __restrict__ vp,
                           const float* __restrict__ vs,
                           const float* __restrict__ rho,
                           const float* __restrict__ theta,
                           const float* __restrict__ W) {
    int gidx = blockIdx.x * 256 + threadIdx.x;

    if (gidx >= HTOTAL) {
        int idx = gidx - HTOTAL;
        if (idx < WELEMS) {
            int r = idx >> 8, k = idx & 255;
            float v = (r < L_LAYERS && k < L_LAYERS) ? W[r * L_LAYERS + k] : 0.f;
            g_Wh[idx] = __float2half(v);
        }
        return;
    }

    __shared__ float s_sth[N_THETA], s_cth[N_THETA];
    int tid = threadIdx.x;
    if (tid < N_THETA) {
        float sv, cv;
        sincosf(theta[tid], &sv, &cv);
        s_sth[tid] = sv;
        s_cth[tid] = cv;
    }
    __syncthreads();

    int l   = gidx / (NCOL / 2);
    int rem = gidx - l * (NCOL / 2);
    int t   = rem / (N_THETA / 2);
    int ap  = rem - t * (N_THETA / 2);
    int a0  = ap * 2;
    int n   = t * N_THETA + a0;

    float a1 = vp[l * N_TRACES + t],  a2 = vp[(l + 1) * N_TRACES + t];
    float b1 = vs[l * N_TRACES + t],  b2 = vs[(l + 1) * N_TRACES + t];
    float r1 = rho[l * N_TRACES + t], r2 = rho[(l + 1) * N_TRACES + t];

    float inva1 = __fdividef(1.f, a1);
    float k1 = 2.f * r1 * (b1 * b1);
    float k2 = 2.f * r2 * (b2 * b2);
    float d  = k2 - k1;
    float drho = r2 - r1;
    float a1b2 = a1 * b2;
    float a2b1 = a2 * b1;

    float rv[2];
#pragma unroll
    for (int j = 0; j < 2; j++) {
        float sth = s_sth[a0 + j], cth = s_cth[a0 + j];
        float p  = sth * inva1;
        float p2 = p * p;

        float st2 = p * a2;
        float ct2 = sqrt_approx(fmaxf(1.f - st2 * st2, 0.f));
        float sp1 = p * b1;
        float cp1 = sqrt_approx(fmaxf(1.f - sp1 * sp1, 0.f));
        float sp2 = p * b2;
        float cp2 = sqrt_approx(fmaxf(1.f - sp2 * sp2, 0.f));

        float dp2 = d * p2;
        float A = drho - dp2;
        float B = r2 - dp2;
        float C = r1 + dp2;

        float X = B * cth * a2;
        float Y = C * ct2 * a1;
        float E = X + Y;
        float F = fmaf(B * cp1, b2, C * cp2 * b1);
        float Z = d * cth * cp2;
        float Aa1b2 = A * a1b2;
        float G = Aa1b2 - Z;
        float H = fmaf(-d * ct2, cp1, A * a2b1);
        float D = fmaf(E, F, G * H * p2);
        float num = fmaf(X - Y, F, -(Aa1b2 + Z) * H * p2);

        rv[j] = __fdividef(num, D);
    }

    size_t o = ((size_t)l * NP + n) >> 1;
    reinterpret_cast<__half2*>(g_Rh)[o] =
        __halves2half2(__float2half(rv[0]), __float2half(rv[1]));
}

// ---------------------------------------------------------------------------
// Phase 2: out[t, l, a] = sum_k W[l, k] * R[k, n], n = t*30 + a
// Pure-fp16 HMMA GEMM, SINGLE-SHOT: the whole K=256 is resident in smem.
// Block = 128(M) x 128(N) output tile, 256 threads (8 warps 4m x 2n),
// warp tile 32x64, m16n8k16.
// One cp.async burst (32 CP16/thread) -> one wait -> ONE __syncthreads ->
// fully unrolled 16 k-step ldsm/mma stream with NO barriers.
// smem: A[128][APITCH=264] + B[256][BPITCH=136] = 137216 B -> 1 block/SM.
// ---------------------------------------------------------------------------
#define APITCH 264                   // 256 + 8 pad halves (528B rows)
#define BPITCH 136                   // 128 + 8 pad halves (272B rows)
#define A_HALVES (128 * APITCH)      // 33792
#define B_HALVES (256 * BPITCH)      // 34816
#define SMEM_BYTES ((A_HALVES + B_HALVES) * 2)   // 137216

__device__ __forceinline__ uint32_t smaddr(const void* p) {
    return (uint32_t)__cvta_generic_to_shared(p);
}
__device__ __forceinline__ void ldsm4(uint32_t a[4], uint32_t addr) {
    asm volatile("ldmatrix.sync.aligned.m8n8.x4.shared.b16 {%0,%1,%2,%3}, [%4];"
                 : "=r"(a[0]), "=r"(a[1]), "=r"(a[2]), "=r"(a[3]) : "r"(addr));
}
__device__ __forceinline__ void ldsm4t(uint32_t a[4], uint32_t addr) {
    asm volatile("ldmatrix.sync.aligned.m8n8.x4.trans.shared.b16 {%0,%1,%2,%3}, [%4];"
                 : "=r"(a[0]), "=r"(a[1]), "=r"(a[2]), "=r"(a[3]) : "r"(addr));
}
__device__ __forceinline__ void mma16816(float c[4], const uint32_t a[4], const uint32_t b[2]) {
    asm volatile("mma.sync.aligned.m16n8k16.row.col.f32.f16.f16.f32 "
                 "{%0,%1,%2,%3}, {%4,%5,%6,%7}, {%8,%9}, {%0,%1,%2,%3};"
                 : "+f"(c[0]), "+f"(c[1]), "+f"(c[2]), "+f"(c[3])
                 : "r"(a[0]), "r"(a[1]), "r"(a[2]), "r"(a[3]), "r"(b[0]), "r"(b[1]));
}
#define CP16(dst, src) \
    asm volatile("cp.async.ca.shared.global [%0], [%1], 16;" :: "r"(dst), "l"(src))
#define CP_COMMIT() asm volatile("cp.async.commit_group;")
#define CP_WAIT0()  asm volatile("cp.async.wait_group 0;")

__global__ __launch_bounds__(256, 1)
void zoe_gemm(float* __restrict__ out) {
    extern __shared__ __half sm[];
    __half* As = sm;                      // A_HALVES
    __half* Bs = sm + A_HALVES;           // B_HALVES

    int tid = threadIdx.x;
    int bm = blockIdx.y * 128;
    int bn = blockIdx.x * 128;

    // ---- single-shot fill ----
    // A: 128 rows x 256 k; 32 CP16/row -> thread covers rows tid>>1,
    //    halves of row: (tid&1)*128, 16 CP16 each.
    {
        int m  = tid >> 1;
        int k0 = (tid & 1) * 128;
        const __half* srcA = &g_Wh[(bm + m) * 256 + k0];
        uint32_t dstA = smaddr(&As[m * APITCH + k0]);
#pragma unroll
        for (int c = 0; c < 16; c++)
            CP16(dstA + c * 16, srcA + c * 8);
    }
    // B: 256 k-rows x 128 n; 16 CP16/row -> thread covers k = tid, tid+... :
    //    256 rows / 256 threads = 1 row each, 16 CP16.
    {
        int k = tid;
        const __half* srcB = &g_Rh[(size_t)k * NP + bn];
        uint32_t dstB = smaddr(&Bs[k * BPITCH]);
#pragma unroll
        for (int c = 0; c < 16; c++)
            CP16(dstB + c * 16, srcB + c * 8);
    }
    CP_COMMIT();

    // ---- warp tiling: 8 warps 4m x 2n, warp tile 32(M) x 64(N) ----
    int wid = tid >> 5, lane = tid & 31;
    int wm = (wid >> 1) * 32;                  // 0,32,64,96
    int wn = (wid & 1) * 64;                   // 0 or 64
    int r8 = lane >> 3, i8 = lane & 7;
    int a_frow = wm + (r8 & 1) * 8 + i8;       // + mt*16
    int a_fcol = (r8 >> 1) * 8;                // + ks*16
    int b_fkrow = (r8 & 1) * 8 + i8;           // + ks*16
    int b_fncol = wn + (r8 >> 1) * 8;          // + pair*16

    uint32_t sAf = smaddr(&As[a_frow * APITCH + a_fcol]);
    uint32_t sBf = smaddr(&Bs[b_fkrow * BPITCH + b_fncol]);

    float acc[2][8][4];
#pragma unroll
    for (int mt = 0; mt < 2; mt++)
#pragma unroll
        for (int nt = 0; nt < 8; nt++)
#pragma unroll
            for (int e = 0; e < 4; e++) acc[mt][nt][e] = 0.f;

    CP_WAIT0();
    __syncthreads();                           // the ONLY barrier

    // ---- fully unrolled 16 k-steps, no barriers ----
#pragma unroll
    for (int ks = 0; ks < 16; ks++) {
        uint32_t bhf[8][2];
#pragma unroll
        for (int pair = 0; pair < 4; pair++) {
            uint32_t t4[4];
            ldsm4t(t4, sBf + ks * 16 * (BPITCH * 2) + pair * 32);
            bhf[pair * 2][0] = t4[0]; bhf[pair * 2][1] = t4[1];
            bhf[pair * 2 + 1][0] = t4[2]; bhf[pair * 2 + 1][1] = t4[3];
        }
#pragma unroll
        for (int mt = 0; mt < 2; mt++) {
            uint32_t ahf[4];
            ldsm4(ahf, sAf + mt * 16 * (APITCH * 2) + ks * 32);
#pragma unroll
            for (int nt = 0; nt < 8; nt++) {
                mma16816(acc[mt][nt], ahf, bhf[nt]);
            }
        }
    }

    // ---- epilogue ----
#pragma unroll
    for (int mt = 0; mt < 2; mt++) {
#pragma unroll
        for (int nt = 0; nt < 8; nt++) {
            int l0 = bm + wm + mt * 16 + (lane >> 2);
            int n0 = bn + wn + nt * 8 + (lane & 3) * 2;
#pragma unroll
            for (int e = 0; e < 4; e++) {
                int l = l0 + (e >> 1) * 8;
                int n = n0 + (e & 1);
                if (l < L_LAYERS && n < NCOL) {
                    int t = n / N_THETA;
                    int a = n - t * N_THETA;
                    out[t * (L_LAYERS * N_THETA) + l * N_THETA + a] = acc[mt][nt][e];
                }
            }
        }
    }
}

extern "C" void kernel_launch(void* const* d_in, const int* in_sizes, int n_in,
                              void* d_out, int out_size) {
    const float* vp      = (const float*)d_in[0];
    const float* vs      = (const float*)d_in[1];
    const float* rho     = (const float*)d_in[2];
    const float* theta   = (const float*)d_in[3];
    const float* wavemat = (const float*)d_in[4];
    float* out = (float*)d_out;

    cudaFuncSetAttribute(zoe_gemm, cudaFuncAttributeMaxDynamicSharedMemorySize,
                         SMEM_BYTES);

    int nblk = (HTOTAL + WELEMS + 255) / 256;
    zoe_phase1<<<nblk, 256>>>(vp, vs, rho, theta, wavemat);

    dim3 grid((NCOL + 127) / 128, 2);
    zoe_gemm<<<grid, 256, SMEM_BYTES>>>(out);
}